// round 10
// baseline (speedup 1.0000x reference)
#include <cuda_runtime.h>
#include <stdint.h>

// Problem constants (from reference setup_inputs)
#define B_DIM 32
#define T_DIM 512
#define D_DIM 384
#define DUR_MAX 8
#define T_OUT (T_DIM * DUR_MAX)   // 4096
#define D4 (D_DIM / 4)            // 96 float4 per frame
#define NTILE ((B_DIM * T_OUT) / 32)   // 4096 tiles of 32 frames
#define PERSIST_BLOCKS 740             // 148 SMs x 5 CTAs -> exactly one wave

// Scratch (allocation-free rule: __device__ globals)
__device__ int g_total;
__device__ int g_idx[B_DIM * T_OUT];   // frame -> phoneme index, -1 = pad

// ---------------------------------------------------------------------------
// Fused prep kernel: grid = 33 blocks, 512 threads.
//   block 32     : global duration sum -> g_total
//   blocks 0..31 : per-row shfl scan + scatter idx map
// Fires the programmatic-launch trigger right after the last global write.
// ---------------------------------------------------------------------------
__global__ void __launch_bounds__(T_DIM) prep_kernel(const int* __restrict__ dur) {
    const int b = blockIdx.x;
    const int j = threadIdx.x;

    if (b == B_DIM) {
        const int4* d4 = (const int4*)dur;          // 4096 int4
        int sum = 0;
        #pragma unroll
        for (int i = 0; i < 8; ++i) {
            int4 v = d4[j + i * T_DIM];
            sum += v.x + v.y + v.z + v.w;
        }
        #pragma unroll
        for (int off = 16; off > 0; off >>= 1)
            sum += __shfl_down_sync(0xffffffffu, sum, off);
        __shared__ int sw[16];
        if ((j & 31) == 0) sw[j >> 5] = sum;
        __syncthreads();
        if (j < 16) {
            int s = sw[j];
            #pragma unroll
            for (int off = 8; off > 0; off >>= 1)
                s += __shfl_down_sync(0xffffu, s, off);
            if (j == 0) g_total = s;
        }
        cudaTriggerProgrammaticLaunchCompletion();
        return;
    }

    // ---- per-row inclusive scan of durations ----
    const int lane = j & 31;
    const int wid  = j >> 5;                        // 16 warps
    int d = dur[b * T_DIM + j];

    int x = d;
    #pragma unroll
    for (int off = 1; off < 32; off <<= 1) {
        int v = __shfl_up_sync(0xffffffffu, x, off);
        if (lane >= off) x += v;
    }

    __shared__ int warpsum[16];
    __shared__ int warppre[16];
    if (lane == 31) warpsum[wid] = x;
    __syncthreads();
    if (j < 16) {
        int v = warpsum[j];
        int p = v;
        #pragma unroll
        for (int off = 1; off < 16; off <<= 1) {
            int t = __shfl_up_sync(0xffffu, p, off);
            if (j >= off) p += t;
        }
        warppre[j] = p - v;                         // exclusive prefix of warp sums
    }
    __syncthreads();

    const int end   = x + warppre[wid];             // inclusive cumsum
    const int start = end - d;
    int* __restrict__ idx = g_idx + b * T_OUT;
    for (int k = start; k < end; ++k) idx[k] = j;

    __shared__ int s_total;
    if (j == T_DIM - 1) s_total = end;
    __syncthreads();
    for (int t = s_total + j; t < T_OUT; t += T_DIM) idx[t] = -1;

    cudaTriggerProgrammaticLaunchCompletion();
}

// ---------------------------------------------------------------------------
// PERSISTENT gather: one wave of 740 blocks; each block grid-strides over
// 4096 tiles of 32 frames. Per-tile body identical to the proven 35.5us
// config (8 contiguous frames/thread, idx via 2x LDG.128, .cs stores).
// Eliminates wave transitions and partial-wave tail.
// ---------------------------------------------------------------------------
__global__ void __launch_bounds__(D4 * 4) gather_kernel(
    const float4* __restrict__ xs, float4* __restrict__ out)
{
    const int t     = threadIdx.x;                  // 0..383
    const int y     = t / D4;                       // 0..3
    const int lane  = t - y * D4;                   // 0..95

    // PDL: wait until prep_kernel's writes (g_idx, g_total) are visible.
    cudaGridDependencySynchronize();
    const int tot = g_total;

    for (int tile = blockIdx.x; tile < NTILE; tile += PERSIST_BLOCKS) {
        const int base = tile * 32 + y * 8;         // first of 8 contiguous frames
        const int bb   = base >> 12;                // batch row (/ T_OUT)
        const int tloc = base & (T_OUT - 1);        // frame-in-row of k=0
        const float4* xrow = xs + bb * (T_DIM * D4) + lane;
        float4* op = out + (size_t)base * D4 + lane;

        const int4* ip = (const int4*)(g_idx + base);
        int4 i0 = __ldg(ip);
        int4 i1 = __ldg(ip + 1);
        int id[8] = { i0.x, i0.y, i0.z, i0.w, i1.x, i1.y, i1.z, i1.w };

        if (tot == 0) {                             // all-zero durations edge case
            #pragma unroll
            for (int k = 0; k < 8; ++k)
                if (id[k] < 0 && (tloc + k) < T_DIM) id[k] = tloc + k;
        }

        float4 v[8];
        #pragma unroll
        for (int k = 0; k < 8; ++k) {
            v[k] = make_float4(0.f, 0.f, 0.f, 0.f);
            if (id[k] >= 0) v[k] = __ldg(xrow + id[k] * D4);
        }

        #pragma unroll
        for (int k = 0; k < 8; ++k)
            asm volatile("st.global.cs.v4.f32 [%0], {%1,%2,%3,%4};"
                         :: "l"(op + k * D4),
                            "f"(v[k].x), "f"(v[k].y), "f"(v[k].z), "f"(v[k].w)
                         : "memory");
    }
}

// ---------------------------------------------------------------------------
extern "C" void kernel_launch(void* const* d_in, const int* in_sizes, int n_in,
                              void* d_out, int out_size) {
    const float* xs  = (const float*)d_in[0];   // [B, T, D] f32
    const int*   dur = (const int*)d_in[1];     // [B, T] i32
    float* out = (float*)d_out;                 // [B, T_OUT, D] f32
    (void)in_sizes; (void)n_in; (void)out_size;

    prep_kernel<<<B_DIM + 1, T_DIM>>>(dur);

    // Persistent gather with programmatic dependent launch.
    cudaLaunchConfig_t cfg = {};
    cfg.gridDim  = dim3(PERSIST_BLOCKS);        // exactly one wave
    cfg.blockDim = dim3(D4 * 4);                // 384 threads
    cfg.dynamicSmemBytes = 0;
    cfg.stream = 0;
    cudaLaunchAttribute attr[1];
    attr[0].id = cudaLaunchAttributeProgrammaticStreamSerialization;
    attr[0].val.programmaticStreamSerializationAllowed = 1;
    cfg.attrs = attr;
    cfg.numAttrs = 1;
    cudaLaunchKernelEx(&cfg, gather_kernel, (const float4*)xs, (float4*)out);
}

// round 11
// speedup vs baseline: 1.0557x; 1.0557x over previous
#include <cuda_runtime.h>
#include <stdint.h>

// Problem constants (from reference setup_inputs)
#define B_DIM 32
#define T_DIM 512
#define D_DIM 384
#define DUR_MAX 8
#define T_OUT (T_DIM * DUR_MAX)   // 4096
#define D4 (D_DIM / 4)            // 96 float4 per frame

// Scratch (allocation-free rule: __device__ globals)
__device__ int g_total;
__device__ int g_idx[B_DIM * T_OUT];   // frame -> phoneme index, -1 = pad

// ---------------------------------------------------------------------------
// Fused prep kernel: grid = 33 blocks, 512 threads.
//   block 32     : global duration sum -> g_total
//   blocks 0..31 : per-row shfl scan + scatter idx map
// Fires the programmatic-launch trigger right after the last global write.
// ---------------------------------------------------------------------------
__global__ void __launch_bounds__(T_DIM) prep_kernel(const int* __restrict__ dur) {
    const int b = blockIdx.x;
    const int j = threadIdx.x;

    if (b == B_DIM) {
        const int4* d4 = (const int4*)dur;          // 4096 int4
        int sum = 0;
        #pragma unroll
        for (int i = 0; i < 8; ++i) {
            int4 v = d4[j + i * T_DIM];
            sum += v.x + v.y + v.z + v.w;
        }
        #pragma unroll
        for (int off = 16; off > 0; off >>= 1)
            sum += __shfl_down_sync(0xffffffffu, sum, off);
        __shared__ int sw[16];
        if ((j & 31) == 0) sw[j >> 5] = sum;
        __syncthreads();
        if (j < 16) {
            int s = sw[j];
            #pragma unroll
            for (int off = 8; off > 0; off >>= 1)
                s += __shfl_down_sync(0xffffu, s, off);
            if (j == 0) g_total = s;
        }
        cudaTriggerProgrammaticLaunchCompletion();
        return;
    }

    // ---- per-row inclusive scan of durations ----
    const int lane = j & 31;
    const int wid  = j >> 5;                        // 16 warps
    int d = dur[b * T_DIM + j];

    int x = d;
    #pragma unroll
    for (int off = 1; off < 32; off <<= 1) {
        int v = __shfl_up_sync(0xffffffffu, x, off);
        if (lane >= off) x += v;
    }

    __shared__ int warpsum[16];
    __shared__ int warppre[16];
    if (lane == 31) warpsum[wid] = x;
    __syncthreads();
    if (j < 16) {
        int v = warpsum[j];
        int p = v;
        #pragma unroll
        for (int off = 1; off < 16; off <<= 1) {
            int t = __shfl_up_sync(0xffffu, p, off);
            if (j >= off) p += t;
        }
        warppre[j] = p - v;                         // exclusive prefix of warp sums
    }
    __syncthreads();

    const int end   = x + warppre[wid];             // inclusive cumsum
    const int start = end - d;
    int* __restrict__ idx = g_idx + b * T_OUT;
    for (int k = start; k < end; ++k) idx[k] = j;

    __shared__ int s_total;
    if (j == T_DIM - 1) s_total = end;
    __syncthreads();
    for (int t = s_total + j; t < T_OUT; t += T_DIM) idx[t] = -1;

    cudaTriggerProgrammaticLaunchCompletion();
}

// ---------------------------------------------------------------------------
// Gather: R9 body, 2 tiles per block. Each thread owns 16 contiguous frames
// (two 8-frame batches); ALL four idx int4 loads issued up front (MLP_p1=4 on
// the latency-critical index fetch), then batch-wise gather + .cs stores.
// Grid = 2048 blocks (fixed mapping, no grid-stride loop).
// ---------------------------------------------------------------------------
__global__ void __launch_bounds__(D4 * 4) gather_kernel(
    const float4* __restrict__ xs, float4* __restrict__ out)
{
    const int t     = threadIdx.x;                  // 0..383
    const int y     = t / D4;                       // 0..3
    const int lane  = t - y * D4;                   // 0..95
    const int base  = blockIdx.x * 64 + y * 16;     // first of 16 contiguous frames
    const int bb    = base >> 12;                   // batch row (/ T_OUT)
    const int tloc  = base & (T_OUT - 1);           // frame-in-row of k=0
    const float4* xrow = xs + bb * (T_DIM * D4) + lane;
    float4* op = out + (size_t)base * D4 + lane;

    // PDL: wait until prep_kernel's writes (g_idx, g_total) are visible.
    cudaGridDependencySynchronize();

    const int tot = g_total;

    // 16 indices via four int4 loads, all issued up front (base % 16 == 0)
    const int4* ip = (const int4*)(g_idx + base);
    int4 i0 = __ldg(ip);
    int4 i1 = __ldg(ip + 1);
    int4 i2 = __ldg(ip + 2);
    int4 i3 = __ldg(ip + 3);
    int id[16] = { i0.x, i0.y, i0.z, i0.w, i1.x, i1.y, i1.z, i1.w,
                   i2.x, i2.y, i2.z, i2.w, i3.x, i3.y, i3.z, i3.w };

    if (tot == 0) {                                 // all-zero durations edge case
        #pragma unroll
        for (int k = 0; k < 16; ++k)
            if (id[k] < 0 && (tloc + k) < T_DIM) id[k] = tloc + k;
    }

    #pragma unroll
    for (int half = 0; half < 2; ++half) {
        float4 v[8];
        #pragma unroll
        for (int k = 0; k < 8; ++k) {
            const int i = id[half * 8 + k];
            v[k] = make_float4(0.f, 0.f, 0.f, 0.f);
            if (i >= 0) v[k] = __ldg(xrow + i * D4);
        }
        #pragma unroll
        for (int k = 0; k < 8; ++k)
            asm volatile("st.global.cs.v4.f32 [%0], {%1,%2,%3,%4};"
                         :: "l"(op + (half * 8 + k) * D4),
                            "f"(v[k].x), "f"(v[k].y), "f"(v[k].z), "f"(v[k].w)
                         : "memory");
    }
}

// ---------------------------------------------------------------------------
extern "C" void kernel_launch(void* const* d_in, const int* in_sizes, int n_in,
                              void* d_out, int out_size) {
    const float* xs  = (const float*)d_in[0];   // [B, T, D] f32
    const int*   dur = (const int*)d_in[1];     // [B, T] i32
    float* out = (float*)d_out;                 // [B, T_OUT, D] f32
    (void)in_sizes; (void)n_in; (void)out_size;

    prep_kernel<<<B_DIM + 1, T_DIM>>>(dur);

    // Gather with programmatic dependent launch.
    cudaLaunchConfig_t cfg = {};
    cfg.gridDim  = dim3((B_DIM * T_OUT) / 64);  // 2048 blocks
    cfg.blockDim = dim3(D4 * 4);                // 384 threads
    cfg.dynamicSmemBytes = 0;
    cfg.stream = 0;
    cudaLaunchAttribute attr[1];
    attr[0].id = cudaLaunchAttributeProgrammaticStreamSerialization;
    attr[0].val.programmaticStreamSerializationAllowed = 1;
    cfg.attrs = attr;
    cfg.numAttrs = 1;
    cudaLaunchKernelEx(&cfg, gather_kernel, (const float4*)xs, (float4*)out);
}

// round 12
// speedup vs baseline: 1.0676x; 1.0113x over previous
#include <cuda_runtime.h>
#include <stdint.h>

// Problem constants (from reference setup_inputs)
#define B_DIM 32
#define T_DIM 512
#define D_DIM 384
#define DUR_MAX 8
#define T_OUT (T_DIM * DUR_MAX)   // 4096
#define D4 (D_DIM / 4)            // 96 float4 per frame

// Scratch (allocation-free rule: __device__ globals)
__device__ int g_total;
__device__ int g_idx[B_DIM * T_OUT];   // frame -> phoneme index, -1 = pad

// ---------------------------------------------------------------------------
// Fused prep kernel: grid = 33 blocks, 512 threads.
//   block 32     : global duration sum -> g_total
//   blocks 0..31 : per-row shfl scan + scatter idx map
// Fires the programmatic-launch trigger right after the last global write.
// ---------------------------------------------------------------------------
__global__ void __launch_bounds__(T_DIM) prep_kernel(const int* __restrict__ dur) {
    const int b = blockIdx.x;
    const int j = threadIdx.x;

    if (b == B_DIM) {
        const int4* d4 = (const int4*)dur;          // 4096 int4
        int sum = 0;
        #pragma unroll
        for (int i = 0; i < 8; ++i) {
            int4 v = d4[j + i * T_DIM];
            sum += v.x + v.y + v.z + v.w;
        }
        #pragma unroll
        for (int off = 16; off > 0; off >>= 1)
            sum += __shfl_down_sync(0xffffffffu, sum, off);
        __shared__ int sw[16];
        if ((j & 31) == 0) sw[j >> 5] = sum;
        __syncthreads();
        if (j < 16) {
            int s = sw[j];
            #pragma unroll
            for (int off = 8; off > 0; off >>= 1)
                s += __shfl_down_sync(0xffffu, s, off);
            if (j == 0) g_total = s;
        }
        cudaTriggerProgrammaticLaunchCompletion();
        return;
    }

    // ---- per-row inclusive scan of durations ----
    const int lane = j & 31;
    const int wid  = j >> 5;                        // 16 warps
    int d = dur[b * T_DIM + j];

    int x = d;
    #pragma unroll
    for (int off = 1; off < 32; off <<= 1) {
        int v = __shfl_up_sync(0xffffffffu, x, off);
        if (lane >= off) x += v;
    }

    __shared__ int warpsum[16];
    __shared__ int warppre[16];
    if (lane == 31) warpsum[wid] = x;
    __syncthreads();
    if (j < 16) {
        int v = warpsum[j];
        int p = v;
        #pragma unroll
        for (int off = 1; off < 16; off <<= 1) {
            int t = __shfl_up_sync(0xffffu, p, off);
            if (j >= off) p += t;
        }
        warppre[j] = p - v;                         // exclusive prefix of warp sums
    }
    __syncthreads();

    const int end   = x + warppre[wid];             // inclusive cumsum
    const int start = end - d;
    int* __restrict__ idx = g_idx + b * T_OUT;
    for (int k = start; k < end; ++k) idx[k] = j;

    __shared__ int s_total;
    if (j == T_DIM - 1) s_total = end;
    __syncthreads();
    for (int t = s_total + j; t < T_OUT; t += T_DIM) idx[t] = -1;

    cudaTriggerProgrammaticLaunchCompletion();
}

// ---------------------------------------------------------------------------
// Gather (proven best = LTS-cap wall): each thread owns 8 CONTIGUOUS frames,
// idx via two LDG.128, 8 independent gather+store (.cs) pairs.
// Launched with PDL; syncs on prep's programmatic trigger before reading.
// ---------------------------------------------------------------------------
__global__ void __launch_bounds__(D4 * 4) gather_kernel(
    const float4* __restrict__ xs, float4* __restrict__ out)
{
    const int t     = threadIdx.x;                  // 0..383
    const int y     = t / D4;                       // 0..3
    const int lane  = t - y * D4;                   // 0..95
    const int base  = blockIdx.x * 32 + y * 8;      // first of 8 contiguous frames
    const int bb    = base >> 12;                   // batch row (/ T_OUT)
    const int tloc  = base & (T_OUT - 1);           // frame-in-row of k=0
    const float4* xrow = xs + bb * (T_DIM * D4) + lane;
    float4* op = out + (size_t)base * D4 + lane;

    // PDL: wait until prep_kernel's writes (g_idx, g_total) are visible.
    cudaGridDependencySynchronize();

    const int tot = g_total;

    // 8 indices via two int4 loads (base % 8 == 0 -> 16B aligned)
    const int4* ip = (const int4*)(g_idx + base);
    int4 i0 = __ldg(ip);
    int4 i1 = __ldg(ip + 1);
    int id[8] = { i0.x, i0.y, i0.z, i0.w, i1.x, i1.y, i1.z, i1.w };

    if (tot == 0) {                                 // all-zero durations edge case
        #pragma unroll
        for (int k = 0; k < 8; ++k)
            if (id[k] < 0 && (tloc + k) < T_DIM) id[k] = tloc + k;
    }

    float4 v[8];
    #pragma unroll
    for (int k = 0; k < 8; ++k) {
        v[k] = make_float4(0.f, 0.f, 0.f, 0.f);
        if (id[k] >= 0) v[k] = __ldg(xrow + id[k] * D4);
    }

    #pragma unroll
    for (int k = 0; k < 8; ++k)
        asm volatile("st.global.cs.v4.f32 [%0], {%1,%2,%3,%4};"
                     :: "l"(op + k * D4),
                        "f"(v[k].x), "f"(v[k].y), "f"(v[k].z), "f"(v[k].w)
                     : "memory");
}

// ---------------------------------------------------------------------------
extern "C" void kernel_launch(void* const* d_in, const int* in_sizes, int n_in,
                              void* d_out, int out_size) {
    const float* xs  = (const float*)d_in[0];   // [B, T, D] f32
    const int*   dur = (const int*)d_in[1];     // [B, T] i32
    float* out = (float*)d_out;                 // [B, T_OUT, D] f32
    (void)in_sizes; (void)n_in; (void)out_size;

    prep_kernel<<<B_DIM + 1, T_DIM>>>(dur);

    // Gather with programmatic dependent launch: overlaps launch with prep tail.
    cudaLaunchConfig_t cfg = {};
    cfg.gridDim  = dim3((B_DIM * T_OUT) / 32);  // 4096 blocks
    cfg.blockDim = dim3(D4 * 4);                // 384 threads
    cfg.dynamicSmemBytes = 0;
    cfg.stream = 0;
    cudaLaunchAttribute attr[1];
    attr[0].id = cudaLaunchAttributeProgrammaticStreamSerialization;
    attr[0].val.programmaticStreamSerializationAllowed = 1;
    cfg.attrs = attr;
    cfg.numAttrs = 1;
    cudaLaunchKernelEx(&cfg, gather_kernel, (const float4*)xs, (float4*)out);
}

// round 13
// speedup vs baseline: 1.1170x; 1.0462x over previous
#include <cuda_runtime.h>
#include <stdint.h>

// Problem constants (from reference setup_inputs)
#define B_DIM 32
#define T_DIM 512
#define D_DIM 384
#define DUR_MAX 8
#define T_OUT (T_DIM * DUR_MAX)   // 4096
#define D4 (D_DIM / 4)            // 96 float4 per frame

// Scratch (allocation-free rule: __device__ globals)
__device__ int g_total;
__device__ int g_idx[B_DIM * T_OUT];   // frame -> phoneme index, -1 = pad

// ---------------------------------------------------------------------------
// Fused prep kernel: grid = 33 blocks, 512 threads.
//   block 32     : global duration sum -> g_total
//   blocks 0..31 : per-row shfl scan + scatter idx map
// Fires the programmatic-launch trigger right after the last global write.
// ---------------------------------------------------------------------------
__global__ void __launch_bounds__(T_DIM) prep_kernel(const int* __restrict__ dur) {
    const int b = blockIdx.x;
    const int j = threadIdx.x;

    if (b == B_DIM) {
        const int4* d4 = (const int4*)dur;          // 4096 int4
        int sum = 0;
        #pragma unroll
        for (int i = 0; i < 8; ++i) {
            int4 v = d4[j + i * T_DIM];
            sum += v.x + v.y + v.z + v.w;
        }
        #pragma unroll
        for (int off = 16; off > 0; off >>= 1)
            sum += __shfl_down_sync(0xffffffffu, sum, off);
        __shared__ int sw[16];
        if ((j & 31) == 0) sw[j >> 5] = sum;
        __syncthreads();
        if (j < 16) {
            int s = sw[j];
            #pragma unroll
            for (int off = 8; off > 0; off >>= 1)
                s += __shfl_down_sync(0xffffu, s, off);
            if (j == 0) g_total = s;
        }
        cudaTriggerProgrammaticLaunchCompletion();
        return;
    }

    // ---- per-row inclusive scan of durations ----
    const int lane = j & 31;
    const int wid  = j >> 5;                        // 16 warps
    int d = dur[b * T_DIM + j];

    int x = d;
    #pragma unroll
    for (int off = 1; off < 32; off <<= 1) {
        int v = __shfl_up_sync(0xffffffffu, x, off);
        if (lane >= off) x += v;
    }

    __shared__ int warpsum[16];
    __shared__ int warppre[16];
    if (lane == 31) warpsum[wid] = x;
    __syncthreads();
    if (j < 16) {
        int v = warpsum[j];
        int p = v;
        #pragma unroll
        for (int off = 1; off < 16; off <<= 1) {
            int t = __shfl_up_sync(0xffffu, p, off);
            if (j >= off) p += t;
        }
        warppre[j] = p - v;                         // exclusive prefix of warp sums
    }
    __syncthreads();

    const int end   = x + warppre[wid];             // inclusive cumsum
    const int start = end - d;
    int* __restrict__ idx = g_idx + b * T_OUT;
    for (int k = start; k < end; ++k) idx[k] = j;

    __shared__ int s_total;
    if (j == T_DIM - 1) s_total = end;
    __syncthreads();
    for (int t = s_total + j; t < T_OUT; t += T_DIM) idx[t] = -1;

    cudaTriggerProgrammaticLaunchCompletion();
}

// ---------------------------------------------------------------------------
// Gather (proven best = HBM write-mix wall): each thread owns 8 CONTIGUOUS
// frames, idx via two LDG.128, 8 independent gather+store (.cs) pairs.
// Launched with PDL; syncs on prep's programmatic trigger before reading.
// ---------------------------------------------------------------------------
__global__ void __launch_bounds__(D4 * 4) gather_kernel(
    const float4* __restrict__ xs, float4* __restrict__ out)
{
    const int t     = threadIdx.x;                  // 0..383
    const int y     = t / D4;                       // 0..3
    const int lane  = t - y * D4;                   // 0..95
    const int base  = blockIdx.x * 32 + y * 8;      // first of 8 contiguous frames
    const int bb    = base >> 12;                   // batch row (/ T_OUT)
    const int tloc  = base & (T_OUT - 1);           // frame-in-row of k=0
    const float4* xrow = xs + bb * (T_DIM * D4) + lane;
    float4* op = out + (size_t)base * D4 + lane;

    // PDL: wait until prep_kernel's writes (g_idx, g_total) are visible.
    cudaGridDependencySynchronize();

    const int tot = g_total;

    // 8 indices via two int4 loads (base % 8 == 0 -> 16B aligned)
    const int4* ip = (const int4*)(g_idx + base);
    int4 i0 = __ldg(ip);
    int4 i1 = __ldg(ip + 1);
    int id[8] = { i0.x, i0.y, i0.z, i0.w, i1.x, i1.y, i1.z, i1.w };

    if (tot == 0) {                                 // all-zero durations edge case
        #pragma unroll
        for (int k = 0; k < 8; ++k)
            if (id[k] < 0 && (tloc + k) < T_DIM) id[k] = tloc + k;
    }

    float4 v[8];
    #pragma unroll
    for (int k = 0; k < 8; ++k) {
        v[k] = make_float4(0.f, 0.f, 0.f, 0.f);
        if (id[k] >= 0) v[k] = __ldg(xrow + id[k] * D4);
    }

    #pragma unroll
    for (int k = 0; k < 8; ++k)
        asm volatile("st.global.cs.v4.f32 [%0], {%1,%2,%3,%4};"
                     :: "l"(op + k * D4),
                        "f"(v[k].x), "f"(v[k].y), "f"(v[k].z), "f"(v[k].w)
                     : "memory");
}

// ---------------------------------------------------------------------------
extern "C" void kernel_launch(void* const* d_in, const int* in_sizes, int n_in,
                              void* d_out, int out_size) {
    const float* xs  = (const float*)d_in[0];   // [B, T, D] f32
    const int*   dur = (const int*)d_in[1];     // [B, T] i32
    float* out = (float*)d_out;                 // [B, T_OUT, D] f32
    (void)in_sizes; (void)n_in; (void)out_size;

    prep_kernel<<<B_DIM + 1, T_DIM>>>(dur);

    // Gather with programmatic dependent launch: overlaps launch with prep tail.
    cudaLaunchConfig_t cfg = {};
    cfg.gridDim  = dim3((B_DIM * T_OUT) / 32);  // 4096 blocks
    cfg.blockDim = dim3(D4 * 4);                // 384 threads
    cfg.dynamicSmemBytes = 0;
    cfg.stream = 0;
    cudaLaunchAttribute attr[1];
    attr[0].id = cudaLaunchAttributeProgrammaticStreamSerialization;
    attr[0].val.programmaticStreamSerializationAllowed = 1;
    cfg.attrs = attr;
    cfg.numAttrs = 1;
    cudaLaunchKernelEx(&cfg, gather_kernel, (const float4*)xs, (float4*)out);
}